// round 8
// baseline (speedup 1.0000x reference)
#include <cuda_runtime.h>
#include <math_constants.h>
#include <cstdint>

typedef unsigned long long ull;
typedef unsigned int uint;

#define NPTS 65536
#define KK   64
#define CH   64          // chunks over N for kernel A
#define LPB  (NPTS/CH)   // 1024 points per block in kernel A
#define BB   8
#define LOG2E 1.4426950408889634f
#define PI_CONST ((1.0f + 1e-8f) / 65536.0f)
#define INV_DENOM (1.0f / (1.0f + 2e-8f))

// Scratch (device globals: no allocation allowed)
__device__ float g_part[16][CH][KK][4];   // [bt][chunk][k][{S, Sx, Sy, Sz}]
__device__ float g_RT[BB][12];            // 9 R (row major) + 3 T

__device__ __forceinline__ float ex2f(float x) {
    float r; asm("ex2.approx.f32 %0, %1;" : "=f"(r) : "f"(x)); return r;
}
__device__ __forceinline__ float lg2f(float x) {
    float r; asm("lg2.approx.f32 %0, %1;" : "=f"(r) : "f"(x)); return r;
}

// ---- packed f32x2 helpers (Blackwell) ----
__device__ __forceinline__ ull fma2(ull a, ull b, ull c) {
    ull d; asm("fma.rn.f32x2 %0, %1, %2, %3;" : "=l"(d) : "l"(a), "l"(b), "l"(c)); return d;
}
__device__ __forceinline__ ull mul2(ull a, ull b) {
    ull d; asm("mul.rn.f32x2 %0, %1, %2;" : "=l"(d) : "l"(a), "l"(b)); return d;
}
__device__ __forceinline__ ull add2(ull a, ull b) {
    ull d; asm("add.rn.f32x2 %0, %1, %2;" : "=l"(d) : "l"(a), "l"(b)); return d;
}
__device__ __forceinline__ ull pack2(float lo, float hi) {
    ull r; asm("mov.b64 %0, {%1, %2};" : "=l"(r) : "f"(lo), "f"(hi)); return r;
}
// exp2 on both halves of a packed pair via MUFU
__device__ __forceinline__ ull ex2_2(ull v) {
    ull r;
    asm("{\n\t.reg .f32 lo, hi;\n\t"
        "mov.b64 {lo, hi}, %1;\n\t"
        "ex2.approx.f32 lo, lo;\n\t"
        "ex2.approx.f32 hi, hi;\n\t"
        "mov.b64 %0, {lo, hi};\n\t}"
        : "=l"(r) : "l"(v));
    return r;
}

// fp32-accurate packed exp2 on the FMA+ALU pipes (no MUFU).
// Range reduction via add-magic (RN): n = round(l), r = l - n in [-0.5, 0.5];
// 2^r by deg-4 minimax; 2^n spliced into the exponent with an integer add.
#define MAGICF 12582912.0f   // 1.5 * 2^23
__device__ __forceinline__ ull poly_exp2_2(ull l,
                                           ull MAG2, ull NMAG2, ull NEG1_2,
                                           ull C4, ull C3, ull C2, ull C1, ull C0) {
    ull t = add2(l, MAG2);            // low 23 bits of halves hold round(l)
    ull s = add2(t, NMAG2);           // s = n (as float)
    ull r = fma2(s, NEG1_2, l);       // r = l - n in [-0.5, 0.5]
    ull p = fma2(C4, r, C3);
    p = fma2(p, r, C2);
    p = fma2(p, r, C1);
    p = fma2(p, r, C0);               // p = 2^r
    uint tl = (uint)t, th = (uint)(t >> 32);
    uint pl = (uint)p, ph = (uint)(p >> 32);
    // low 9 bits of float_bits(MAGICF) are 0 -> (bits - magicbits)<<23 == bits<<23
    uint el = pl + (tl << 23);
    uint eh = ph + (th << 23);
    return (ull)el | ((ull)eh << 32);
}

union F4u { float4 f; ull u[2]; };

// ---------------------------------------------------------------------------
// Kernel A: per (b, tensor, chunk): plain-sum softmax numerators for all K=64.
// 256 threads = 16 k-lanes (4 k's each) x 16 point-slots. Hybrid exp: half of
// the pairs use MUFU ex2, half use the fma-pipe polynomial -> balances the
// saturated MUFU pipe (the R5-R7 invariant 28.6us) against fma headroom.
// ---------------------------------------------------------------------------
__global__ void __launch_bounds__(256) kA(const float* __restrict__ tmpl,
                                          const float* __restrict__ src,
                                          const float* __restrict__ W)
{
    __shared__ float sm[4096];   // 16 KB: points in [0,3072); reduce buf reuses
    const int bt = blockIdx.y;
    const int b  = bt & 7;
    const int t  = bt >> 3;
    const float* f = (t ? src : tmpl) + (size_t)b * 3 * NPTS;
    const int base = blockIdx.x * LPB;
    const int tid  = threadIdx.x;

    ((float4*)sm)[tid]       = ((const float4*)(f + base))[tid];
    ((float4*)sm)[256 + tid] = ((const float4*)(f + NPTS + base))[tid];
    ((float4*)sm)[512 + tid] = ((const float4*)(f + 2*NPTS + base))[tid];
    __syncthreads();

    const int kl   = tid & 15;          // k-lane: owns k = kl + 16*j
    const int slot = tid >> 4;          // 0..15, 64 points per slot

    const ull MAG2   = pack2(MAGICF, MAGICF);
    const ull NMAG2  = pack2(-MAGICF, -MAGICF);
    const ull NEG1_2 = pack2(-1.0f, -1.0f);
    const ull C4 = pack2(9.6181291e-3f, 9.6181291e-3f);
    const ull C3 = pack2(5.5504109e-2f, 5.5504109e-2f);
    const ull C2 = pack2(2.4022651e-1f, 2.4022651e-1f);
    const ull C1 = pack2(6.9314718e-1f, 6.9314718e-1f);
    const ull C0 = pack2(1.0f, 1.0f);

    ull wx2[4], wy2[4], wz2[4];
    #pragma unroll
    for (int j = 0; j < 4; j++) {
        int k = kl + 16 * j;
        float wx = W[k]       * LOG2E;
        float wy = W[64 + k]  * LOG2E;
        float wz = W[128 + k] * LOG2E;
        wx2[j] = pack2(wx, wx); wy2[j] = pack2(wy, wy); wz2[j] = pack2(wz, wz);
    }

    ull S2[4]  = {0, 0, 0, 0};
    ull AX2[4] = {0, 0, 0, 0};
    ull AY2[4] = {0, 0, 0, 0};
    ull AZ2[4] = {0, 0, 0, 0};

    const F4u* X = (const F4u*)sm + slot * 16;               // 16 F4u = 64 pts
    const F4u* Y = (const F4u*)(sm + LPB) + slot * 16;
    const F4u* Z = (const F4u*)(sm + 2*LPB) + slot * 16;

    #pragma unroll 4
    for (int i = 0; i < 16; i++) {
        F4u px = X[i], py = Y[i], pz = Z[i];
        #pragma unroll
        for (int j = 0; j < 4; j++) {
            ull l01 = fma2(wx2[j], px.u[0], fma2(wy2[j], py.u[0], mul2(wz2[j], pz.u[0])));
            ull l23 = fma2(wx2[j], px.u[1], fma2(wy2[j], py.u[1], mul2(wz2[j], pz.u[1])));
            ull e01 = ex2_2(l01);                                   // MUFU pair
            ull e23 = poly_exp2_2(l23, MAG2, NMAG2, NEG1_2,
                                  C4, C3, C2, C1, C0);              // FMA pair
            S2[j]  = add2(S2[j], e01);            S2[j]  = add2(S2[j], e23);
            AX2[j] = fma2(e01, px.u[0], AX2[j]);  AX2[j] = fma2(e23, px.u[1], AX2[j]);
            AY2[j] = fma2(e01, py.u[0], AY2[j]);  AY2[j] = fma2(e23, py.u[1], AY2[j]);
            AZ2[j] = fma2(e01, pz.u[0], AZ2[j]);  AZ2[j] = fma2(e23, pz.u[1], AZ2[j]);
        }
    }

    __syncthreads();                     // done reading point smem; reuse as buf
    #pragma unroll
    for (int j = 0; j < 4; j++) {
        float s0, s1, x0, x1, y0, y1, z0, z1;
        asm("mov.b64 {%0, %1}, %2;" : "=f"(s0), "=f"(s1) : "l"(S2[j]));
        asm("mov.b64 {%0, %1}, %2;" : "=f"(x0), "=f"(x1) : "l"(AX2[j]));
        asm("mov.b64 {%0, %1}, %2;" : "=f"(y0), "=f"(y1) : "l"(AY2[j]));
        asm("mov.b64 {%0, %1}, %2;" : "=f"(z0), "=f"(z1) : "l"(AZ2[j]));
        float4 v = make_float4(s0 + s1, x0 + x1, y0 + y1, z0 + z1);
        ((float4*)sm)[slot * 64 + kl + 16 * j] = v;    // buf[slot][k]
    }
    __syncthreads();

    if (tid < 64) {                      // one thread per k: sum 16 slots
        float4 a = ((const float4*)sm)[tid];
        #pragma unroll
        for (int s = 1; s < 16; s++) {
            float4 v = ((const float4*)sm)[s * 64 + tid];
            a.x += v.x; a.y += v.y; a.z += v.z; a.w += v.w;
        }
        *(float4*)g_part[bt][blockIdx.x][tid] = a;
    }
}

// ---------------------------------------------------------------------------
// Kernel BC (fused, wide): one block per batch, 1024 threads.
// ---------------------------------------------------------------------------
__device__ void polar3(const float* Win, float* Q)
{
    float X[9];
    #pragma unroll
    for (int i = 0; i < 9; i++) X[i] = Win[i];
    #pragma unroll 1
    for (int it = 0; it < 18; it++) {
        float c00 = X[4]*X[8] - X[5]*X[7];
        float c01 = X[5]*X[6] - X[3]*X[8];
        float c02 = X[3]*X[7] - X[4]*X[6];
        float c10 = X[2]*X[7] - X[1]*X[8];
        float c11 = X[0]*X[8] - X[2]*X[6];
        float c12 = X[1]*X[6] - X[0]*X[7];
        float c20 = X[1]*X[5] - X[2]*X[4];
        float c21 = X[2]*X[3] - X[0]*X[5];
        float c22 = X[0]*X[4] - X[1]*X[3];
        float det = X[0]*c00 + X[1]*c01 + X[2]*c02;
        float g  = ex2f(-0.3333333333f * lg2f(fabsf(det)));  // |det|^(-1/3)
        float h  = 0.5f * g;
        float h2 = __fdividef(0.5f, g * det);
        X[0] = h*X[0] + h2*c00; X[1] = h*X[1] + h2*c01; X[2] = h*X[2] + h2*c02;
        X[3] = h*X[3] + h2*c10; X[4] = h*X[4] + h2*c11; X[5] = h*X[5] + h2*c12;
        X[6] = h*X[6] + h2*c20; X[7] = h*X[7] + h2*c21; X[8] = h*X[8] + h2*c22;
    }
    #pragma unroll
    for (int i = 0; i < 9; i++) Q[i] = X[i];
}

__global__ void __launch_bounds__(1024) kBC()
{
    __shared__ float mus[2][KK][3];   // [t][k][d]
    const int b = blockIdx.x;
    const int tid = threadIdx.x;
    const int item  = tid >> 3;       // 0..127
    const int lane8 = tid & 7;
    const int t  = item >> 6;
    const int k  = item & 63;
    const int bt = t * 8 + b;

    float S = 0.f, AX = 0.f, AY = 0.f, AZ = 0.f;
    #pragma unroll
    for (int j = 0; j < 8; j++) {
        float4 p = *(const float4*)g_part[bt][lane8 + 8 * j][k];
        S += p.x; AX += p.y; AY += p.z; AZ += p.w;
    }
    #pragma unroll
    for (int off = 4; off; off >>= 1) {
        S  += __shfl_xor_sync(0xffffffffu, S,  off);
        AX += __shfl_xor_sync(0xffffffffu, AX, off);
        AY += __shfl_xor_sync(0xffffffffu, AY, off);
        AZ += __shfl_xor_sync(0xffffffffu, AZ, off);
    }
    if (lane8 == 0) {
        float inv = INV_DENOM / S;
        mus[t][k][0] = AX * inv;
        mus[t][k][1] = AY * inv;
        mus[t][k][2] = AZ * inv;
    }
    __syncthreads();

    if (tid < 32) {
        const int lane = tid;
        float ms0[3], ms1[3], mt0[3], mt1[3];
        #pragma unroll
        for (int d = 0; d < 3; d++) {
            ms0[d] = mus[1][lane][d];      ms1[d] = mus[1][lane + 32][d];
            mt0[d] = mus[0][lane][d];      mt1[d] = mus[0][lane + 32][d];
        }
        float ss[3], st[3];
        #pragma unroll
        for (int d = 0; d < 3; d++) { ss[d] = ms0[d] + ms1[d]; st[d] = mt0[d] + mt1[d]; }
        #pragma unroll
        for (int off = 16; off; off >>= 1)
            #pragma unroll
            for (int d = 0; d < 3; d++) {
                ss[d] += __shfl_xor_sync(0xffffffffu, ss[d], off);
                st[d] += __shfl_xor_sync(0xffffffffu, st[d], off);
            }
        float cx[3], cy[3];
        #pragma unroll
        for (int d = 0; d < 3; d++) { cx[d] = PI_CONST * ss[d]; cy[d] = PI_CONST * st[d]; }

        float Wm[9];
        #pragma unroll
        for (int d = 0; d < 3; d++)
            #pragma unroll
            for (int e = 0; e < 3; e++)
                Wm[d*3+e] = (mt0[d] - cy[d]) * (ms0[e] - cx[e])
                          + (mt1[d] - cy[d]) * (ms1[e] - cx[e]);
        #pragma unroll
        for (int off = 16; off; off >>= 1)
            #pragma unroll
            for (int i = 0; i < 9; i++)
                Wm[i] += __shfl_xor_sync(0xffffffffu, Wm[i], off);

        if (lane == 0) {
            #pragma unroll
            for (int i = 0; i < 9; i++) Wm[i] *= PI_CONST;
            float Q[9];
            polar3(Wm, Q);
            float det = Q[0]*(Q[4]*Q[8]-Q[5]*Q[7])
                      - Q[1]*(Q[3]*Q[8]-Q[5]*Q[6])
                      + Q[2]*(Q[3]*Q[7]-Q[4]*Q[6]);
            if (det < 0.f) { Q[2] = -Q[2]; Q[5] = -Q[5]; Q[8] = -Q[8]; }
            float T0 = cy[0] - (Q[0]*cx[0] + Q[1]*cx[1] + Q[2]*cx[2]);
            float T1 = cy[1] - (Q[3]*cx[0] + Q[4]*cx[1] + Q[5]*cx[2]);
            float T2 = cy[2] - (Q[6]*cx[0] + Q[7]*cx[1] + Q[8]*cx[2]);
            float* rt = g_RT[b];
            #pragma unroll
            for (int i = 0; i < 9; i++) rt[i] = Q[i];
            rt[9] = T0; rt[10] = T1; rt[11] = T2;
        }
    }
}

// ---------------------------------------------------------------------------
// Kernel D: aligned[b,n,:] = R * src_pts[b,n,:] + T.
// ---------------------------------------------------------------------------
__global__ void __launch_bounds__(256) kD(const float* __restrict__ src,
                                          float* __restrict__ out)
{
    __shared__ float4 so[1536];
    __shared__ float rt[12];
    const int b = blockIdx.x >> 5;
    const int tile = blockIdx.x & 31;
    const int tid = threadIdx.x;

    const float* f = src + (size_t)b * 3 * NPTS + tile * 2048;
    float4 px0 = ((const float4*)f)[tid];
    float4 px1 = ((const float4*)f)[256 + tid];
    float4 py0 = ((const float4*)(f + NPTS))[tid];
    float4 py1 = ((const float4*)(f + NPTS))[256 + tid];
    float4 pz0 = ((const float4*)(f + 2*NPTS))[tid];
    float4 pz1 = ((const float4*)(f + 2*NPTS))[256 + tid];

    if (tid < 12) rt[tid] = g_RT[b][tid];
    __syncthreads();

    float r0 = rt[0], r1 = rt[1], r2 = rt[2];
    float r3 = rt[3], r4 = rt[4], r5 = rt[5];
    float r6 = rt[6], r7 = rt[7], r8 = rt[8];
    float t0 = rt[9], t1 = rt[10], t2 = rt[11];

    #pragma unroll
    for (int h = 0; h < 2; h++) {
        float4 px = h ? px1 : px0, py = h ? py1 : py0, pz = h ? pz1 : pz0;
        float X[4] = {px.x, px.y, px.z, px.w};
        float Y[4] = {py.x, py.y, py.z, py.w};
        float Z[4] = {pz.x, pz.y, pz.z, pz.w};
        float o[12];
        #pragma unroll
        for (int j = 0; j < 4; j++) {
            o[j*3 + 0] = fmaf(r0, X[j], fmaf(r1, Y[j], fmaf(r2, Z[j], t0)));
            o[j*3 + 1] = fmaf(r3, X[j], fmaf(r4, Y[j], fmaf(r5, Z[j], t1)));
            o[j*3 + 2] = fmaf(r6, X[j], fmaf(r7, Y[j], fmaf(r8, Z[j], t2)));
        }
        #pragma unroll
        for (int j = 0; j < 3; j++)
            so[(h * 256 + tid) * 3 + j] = make_float4(o[j*4+0], o[j*4+1], o[j*4+2], o[j*4+3]);
    }
    __syncthreads();

    float4* ob = (float4*)(out + ((size_t)b * NPTS + tile * 2048) * 3);
    #pragma unroll
    for (int i = tid; i < 1536; i += 256) ob[i] = so[i];
}

// ---------------------------------------------------------------------------
extern "C" void kernel_launch(void* const* d_in, const int* in_sizes, int n_in,
                              void* d_out, int out_size)
{
    const float* tmpl = (const float*)d_in[0];   // (8,3,65536)
    const float* src  = (const float*)d_in[1];   // (8,3,65536)
    const float* W    = (const float*)d_in[2];   // (3,64)
    float* out        = (float*)d_out;           // (8,65536,3)

    kA<<<dim3(CH, 16), 256>>>(tmpl, src, W);
    kBC<<<BB, 1024>>>();
    kD<<<256, 256>>>(src, out);
}

// round 9
// speedup vs baseline: 1.1617x; 1.1617x over previous
#include <cuda_runtime.h>
#include <math_constants.h>
#include <cstdint>

typedef unsigned long long ull;
typedef unsigned int uint;

#define NPTS 65536
#define KK   64
#define CH   64          // chunks over N for kernel A
#define LPB  (NPTS/CH)   // 1024 points per block in kernel A
#define BB   8
#define LOG2E 1.4426950408889634f
#define PI_CONST ((1.0f + 1e-8f) / 65536.0f)
#define INV_DENOM (1.0f / (1.0f + 2e-8f))

// Scratch (device globals: no allocation allowed)
__device__ float g_part[16][CH][KK][4];   // [bt][chunk][k][{S, Sx, Sy, Sz}]
__device__ float g_RT[BB][12];            // 9 R (row major) + 3 T

__device__ __forceinline__ float ex2f(float x) {
    float r; asm("ex2.approx.f32 %0, %1;" : "=f"(r) : "f"(x)); return r;
}
__device__ __forceinline__ float lg2f(float x) {
    float r; asm("lg2.approx.f32 %0, %1;" : "=f"(r) : "f"(x)); return r;
}

// ---- packed f32x2 ops (Blackwell FFMA2) ----
__device__ __forceinline__ ull fma2(ull a, ull b, ull c) {
    ull d; asm("fma.rn.f32x2 %0, %1, %2, %3;" : "=l"(d) : "l"(a), "l"(b), "l"(c)); return d;
}
__device__ __forceinline__ ull mul2(ull a, ull b) {
    ull d; asm("mul.rn.f32x2 %0, %1, %2;" : "=l"(d) : "l"(a), "l"(b)); return d;
}
__device__ __forceinline__ ull add2(ull a, ull b) {
    ull d; asm("add.rn.f32x2 %0, %1, %2;" : "=l"(d) : "l"(a), "l"(b)); return d;
}

// Union-based pack/unpack: compiler-visible, maps to register-pair halves
// with ZERO MOV instructions (unlike asm mov.b64 blocks).
union U2 { ull u; float2 f; };
__device__ __forceinline__ ull pack2c(float lo, float hi) {
    U2 t; t.f.x = lo; t.f.y = hi; return t.u;
}

union F4u { float4 f; ull u[2]; };

// ---------------------------------------------------------------------------
// Kernel A: per (b, tensor, chunk): plain-sum softmax numerators for all K=64.
// 256 threads = 16 k-lanes (4 k's each) x 16 point-slots. All packed math via
// FFMA2; exps via scalar ex2 reading register-pair halves through unions
// (no MOV overhead, no asm scheduling barriers).
// ---------------------------------------------------------------------------
__global__ void __launch_bounds__(256) kA(const float* __restrict__ tmpl,
                                          const float* __restrict__ src,
                                          const float* __restrict__ W)
{
    __shared__ float sm[4096];   // 16 KB: points in [0,3072); reduce buf reuses
    const int bt = blockIdx.y;
    const int b  = bt & 7;
    const int t  = bt >> 3;
    const float* f = (t ? src : tmpl) + (size_t)b * 3 * NPTS;
    const int base = blockIdx.x * LPB;
    const int tid  = threadIdx.x;

    ((float4*)sm)[tid]       = ((const float4*)(f + base))[tid];
    ((float4*)sm)[256 + tid] = ((const float4*)(f + NPTS + base))[tid];
    ((float4*)sm)[512 + tid] = ((const float4*)(f + 2*NPTS + base))[tid];
    __syncthreads();

    const int kl   = tid & 15;          // k-lane: owns k = kl + 16*j
    const int slot = tid >> 4;          // 0..15, 64 points per slot

    ull wx2[4], wy2[4], wz2[4];
    #pragma unroll
    for (int j = 0; j < 4; j++) {
        int k = kl + 16 * j;
        float wx = W[k]       * LOG2E;
        float wy = W[64 + k]  * LOG2E;
        float wz = W[128 + k] * LOG2E;
        wx2[j] = pack2c(wx, wx); wy2[j] = pack2c(wy, wy); wz2[j] = pack2c(wz, wz);
    }

    ull S2[4]  = {0, 0, 0, 0};
    ull AX2[4] = {0, 0, 0, 0};
    ull AY2[4] = {0, 0, 0, 0};
    ull AZ2[4] = {0, 0, 0, 0};

    const F4u* X = (const F4u*)sm + slot * 16;               // 16 F4u = 64 pts
    const F4u* Y = (const F4u*)(sm + LPB) + slot * 16;
    const F4u* Z = (const F4u*)(sm + 2*LPB) + slot * 16;

    #pragma unroll 4
    for (int i = 0; i < 16; i++) {
        F4u px = X[i], py = Y[i], pz = Z[i];
        #pragma unroll
        for (int j = 0; j < 4; j++) {
            U2 l01, l23, e01, e23;
            l01.u = fma2(wx2[j], px.u[0], fma2(wy2[j], py.u[0], mul2(wz2[j], pz.u[0])));
            l23.u = fma2(wx2[j], px.u[1], fma2(wy2[j], py.u[1], mul2(wz2[j], pz.u[1])));
            e01.f.x = ex2f(l01.f.x);  e01.f.y = ex2f(l01.f.y);
            e23.f.x = ex2f(l23.f.x);  e23.f.y = ex2f(l23.f.y);
            S2[j]  = add2(S2[j], e01.u);            S2[j]  = add2(S2[j], e23.u);
            AX2[j] = fma2(e01.u, px.u[0], AX2[j]);  AX2[j] = fma2(e23.u, px.u[1], AX2[j]);
            AY2[j] = fma2(e01.u, py.u[0], AY2[j]);  AY2[j] = fma2(e23.u, py.u[1], AY2[j]);
            AZ2[j] = fma2(e01.u, pz.u[0], AZ2[j]);  AZ2[j] = fma2(e23.u, pz.u[1], AZ2[j]);
        }
    }

    __syncthreads();                     // done reading point smem; reuse as buf
    #pragma unroll
    for (int j = 0; j < 4; j++) {
        U2 s, x, y, z;
        s.u = S2[j]; x.u = AX2[j]; y.u = AY2[j]; z.u = AZ2[j];
        float4 v = make_float4(s.f.x + s.f.y, x.f.x + x.f.y,
                               y.f.x + y.f.y, z.f.x + z.f.y);
        ((float4*)sm)[slot * 64 + kl + 16 * j] = v;    // buf[slot][k]
    }
    __syncthreads();

    if (tid < 64) {                      // one thread per k: sum 16 slots
        float4 a = ((const float4*)sm)[tid];
        #pragma unroll
        for (int s = 1; s < 16; s++) {
            float4 v = ((const float4*)sm)[s * 64 + tid];
            a.x += v.x; a.y += v.y; a.z += v.z; a.w += v.w;
        }
        *(float4*)g_part[bt][blockIdx.x][tid] = a;
    }
}

// ---------------------------------------------------------------------------
// Kernel BC (fused, wide): one block per batch, 1024 threads.
// ---------------------------------------------------------------------------
__device__ void polar3(const float* Win, float* Q)
{
    float X[9];
    #pragma unroll
    for (int i = 0; i < 9; i++) X[i] = Win[i];
    #pragma unroll 1
    for (int it = 0; it < 18; it++) {
        float c00 = X[4]*X[8] - X[5]*X[7];
        float c01 = X[5]*X[6] - X[3]*X[8];
        float c02 = X[3]*X[7] - X[4]*X[6];
        float c10 = X[2]*X[7] - X[1]*X[8];
        float c11 = X[0]*X[8] - X[2]*X[6];
        float c12 = X[1]*X[6] - X[0]*X[7];
        float c20 = X[1]*X[5] - X[2]*X[4];
        float c21 = X[2]*X[3] - X[0]*X[5];
        float c22 = X[0]*X[4] - X[1]*X[3];
        float det = X[0]*c00 + X[1]*c01 + X[2]*c02;
        float g  = ex2f(-0.3333333333f * lg2f(fabsf(det)));  // |det|^(-1/3)
        float h  = 0.5f * g;
        float h2 = __fdividef(0.5f, g * det);
        X[0] = h*X[0] + h2*c00; X[1] = h*X[1] + h2*c01; X[2] = h*X[2] + h2*c02;
        X[3] = h*X[3] + h2*c10; X[4] = h*X[4] + h2*c11; X[5] = h*X[5] + h2*c12;
        X[6] = h*X[6] + h2*c20; X[7] = h*X[7] + h2*c21; X[8] = h*X[8] + h2*c22;
    }
    #pragma unroll
    for (int i = 0; i < 9; i++) Q[i] = X[i];
}

__global__ void __launch_bounds__(1024) kBC()
{
    __shared__ float mus[2][KK][3];   // [t][k][d]
    const int b = blockIdx.x;
    const int tid = threadIdx.x;
    const int item  = tid >> 3;       // 0..127
    const int lane8 = tid & 7;
    const int t  = item >> 6;
    const int k  = item & 63;
    const int bt = t * 8 + b;

    float S = 0.f, AX = 0.f, AY = 0.f, AZ = 0.f;
    #pragma unroll
    for (int j = 0; j < 8; j++) {
        float4 p = *(const float4*)g_part[bt][lane8 + 8 * j][k];
        S += p.x; AX += p.y; AY += p.z; AZ += p.w;
    }
    #pragma unroll
    for (int off = 4; off; off >>= 1) {
        S  += __shfl_xor_sync(0xffffffffu, S,  off);
        AX += __shfl_xor_sync(0xffffffffu, AX, off);
        AY += __shfl_xor_sync(0xffffffffu, AY, off);
        AZ += __shfl_xor_sync(0xffffffffu, AZ, off);
    }
    if (lane8 == 0) {
        float inv = INV_DENOM / S;
        mus[t][k][0] = AX * inv;
        mus[t][k][1] = AY * inv;
        mus[t][k][2] = AZ * inv;
    }
    __syncthreads();

    if (tid < 32) {
        const int lane = tid;
        float ms0[3], ms1[3], mt0[3], mt1[3];
        #pragma unroll
        for (int d = 0; d < 3; d++) {
            ms0[d] = mus[1][lane][d];      ms1[d] = mus[1][lane + 32][d];
            mt0[d] = mus[0][lane][d];      mt1[d] = mus[0][lane + 32][d];
        }
        float ss[3], st[3];
        #pragma unroll
        for (int d = 0; d < 3; d++) { ss[d] = ms0[d] + ms1[d]; st[d] = mt0[d] + mt1[d]; }
        #pragma unroll
        for (int off = 16; off; off >>= 1)
            #pragma unroll
            for (int d = 0; d < 3; d++) {
                ss[d] += __shfl_xor_sync(0xffffffffu, ss[d], off);
                st[d] += __shfl_xor_sync(0xffffffffu, st[d], off);
            }
        float cx[3], cy[3];
        #pragma unroll
        for (int d = 0; d < 3; d++) { cx[d] = PI_CONST * ss[d]; cy[d] = PI_CONST * st[d]; }

        float Wm[9];
        #pragma unroll
        for (int d = 0; d < 3; d++)
            #pragma unroll
            for (int e = 0; e < 3; e++)
                Wm[d*3+e] = (mt0[d] - cy[d]) * (ms0[e] - cx[e])
                          + (mt1[d] - cy[d]) * (ms1[e] - cx[e]);
        #pragma unroll
        for (int off = 16; off; off >>= 1)
            #pragma unroll
            for (int i = 0; i < 9; i++)
                Wm[i] += __shfl_xor_sync(0xffffffffu, Wm[i], off);

        if (lane == 0) {
            #pragma unroll
            for (int i = 0; i < 9; i++) Wm[i] *= PI_CONST;
            float Q[9];
            polar3(Wm, Q);
            float det = Q[0]*(Q[4]*Q[8]-Q[5]*Q[7])
                      - Q[1]*(Q[3]*Q[8]-Q[5]*Q[6])
                      + Q[2]*(Q[3]*Q[7]-Q[4]*Q[6]);
            if (det < 0.f) { Q[2] = -Q[2]; Q[5] = -Q[5]; Q[8] = -Q[8]; }
            float T0 = cy[0] - (Q[0]*cx[0] + Q[1]*cx[1] + Q[2]*cx[2]);
            float T1 = cy[1] - (Q[3]*cx[0] + Q[4]*cx[1] + Q[5]*cx[2]);
            float T2 = cy[2] - (Q[6]*cx[0] + Q[7]*cx[1] + Q[8]*cx[2]);
            float* rt = g_RT[b];
            #pragma unroll
            for (int i = 0; i < 9; i++) rt[i] = Q[i];
            rt[9] = T0; rt[10] = T1; rt[11] = T2;
        }
    }
}

// ---------------------------------------------------------------------------
// Kernel D: aligned[b,n,:] = R * src_pts[b,n,:] + T.
// ---------------------------------------------------------------------------
__global__ void __launch_bounds__(256) kD(const float* __restrict__ src,
                                          float* __restrict__ out)
{
    __shared__ float4 so[1536];
    __shared__ float rt[12];
    const int b = blockIdx.x >> 5;
    const int tile = blockIdx.x & 31;
    const int tid = threadIdx.x;

    const float* f = src + (size_t)b * 3 * NPTS + tile * 2048;
    float4 px0 = ((const float4*)f)[tid];
    float4 px1 = ((const float4*)f)[256 + tid];
    float4 py0 = ((const float4*)(f + NPTS))[tid];
    float4 py1 = ((const float4*)(f + NPTS))[256 + tid];
    float4 pz0 = ((const float4*)(f + 2*NPTS))[tid];
    float4 pz1 = ((const float4*)(f + 2*NPTS))[256 + tid];

    if (tid < 12) rt[tid] = g_RT[b][tid];
    __syncthreads();

    float r0 = rt[0], r1 = rt[1], r2 = rt[2];
    float r3 = rt[3], r4 = rt[4], r5 = rt[5];
    float r6 = rt[6], r7 = rt[7], r8 = rt[8];
    float t0 = rt[9], t1 = rt[10], t2 = rt[11];

    #pragma unroll
    for (int h = 0; h < 2; h++) {
        float4 px = h ? px1 : px0, py = h ? py1 : py0, pz = h ? pz1 : pz0;
        float X[4] = {px.x, px.y, px.z, px.w};
        float Y[4] = {py.x, py.y, py.z, py.w};
        float Z[4] = {pz.x, pz.y, pz.z, pz.w};
        float o[12];
        #pragma unroll
        for (int j = 0; j < 4; j++) {
            o[j*3 + 0] = fmaf(r0, X[j], fmaf(r1, Y[j], fmaf(r2, Z[j], t0)));
            o[j*3 + 1] = fmaf(r3, X[j], fmaf(r4, Y[j], fmaf(r5, Z[j], t1)));
            o[j*3 + 2] = fmaf(r6, X[j], fmaf(r7, Y[j], fmaf(r8, Z[j], t2)));
        }
        #pragma unroll
        for (int j = 0; j < 3; j++)
            so[(h * 256 + tid) * 3 + j] = make_float4(o[j*4+0], o[j*4+1], o[j*4+2], o[j*4+3]);
    }
    __syncthreads();

    float4* ob = (float4*)(out + ((size_t)b * NPTS + tile * 2048) * 3);
    #pragma unroll
    for (int i = tid; i < 1536; i += 256) ob[i] = so[i];
}

// ---------------------------------------------------------------------------
extern "C" void kernel_launch(void* const* d_in, const int* in_sizes, int n_in,
                              void* d_out, int out_size)
{
    const float* tmpl = (const float*)d_in[0];   // (8,3,65536)
    const float* src  = (const float*)d_in[1];   // (8,3,65536)
    const float* W    = (const float*)d_in[2];   // (3,64)
    float* out        = (float*)d_out;           // (8,65536,3)

    kA<<<dim3(CH, 16), 256>>>(tmpl, src, W);
    kBC<<<BB, 1024>>>();
    kD<<<256, 256>>>(src, out);
}